// round 15
// baseline (speedup 1.0000x reference)
#include <cuda_runtime.h>
#include <cuda_fp16.h>
#include <cstdint>
#include <math.h>

#define NBATCH 4
#define SEQ    2048
#define DMODEL 512
#define DFFN   2048
#define BSTOT  (NBATCH*SEQ)

// lo-limb pre-scales (power of two)
#define SCL_X  2048.0f        // 2^11
#define SCL_W  524288.0f      // 2^19
#define SCL_KQ 4096.0f        // 2^12

// ---------------- scratch ----------------
__device__ __align__(256) float g_x [BSTOT*DMODEL];
__device__ __align__(256) float g_v [BSTOT*DMODEL];
__device__ __align__(256) float g_at[BSTOT*DMODEL];
__device__ __align__(256) float g_r [BSTOT*DMODEL];
__device__ __align__(256) float g_f2[BSTOT*DMODEL];
__device__ __align__(256) float g_sc[(long long)NBATCH*SEQ*SEQ];
__device__ __align__(256) float g_pos[SEQ*DMODEL];
__device__ __align__(256) float g_bkq[2*DMODEL];

__device__ __align__(256) __half g_xh[BSTOT*DMODEL];
__device__ __align__(256) __half g_kqh[2*BSTOT*DMODEL];
__device__ __align__(256) __half g_vTh[BSTOT*DMODEL];
__device__ __align__(256) __half g_rh[BSTOT*DMODEL];
__device__ __align__(256) __half g_ph[(long long)NBATCH*SEQ*SEQ];
__device__ __align__(256) __half g_f1h[(long long)BSTOT*DFFN];
__device__ __align__(256) __half g_wkqTh[2*DMODEL*DMODEL];
__device__ __align__(256) __half g_wvTh[DMODEL*DMODEL];
__device__ __align__(256) __half g_w1Th[DFFN*DMODEL];
__device__ __align__(256) __half g_w2Th[DMODEL*DFFN];

__device__ __align__(256) uint8_t g_x8h [BSTOT*DMODEL];
__device__ __align__(256) uint8_t g_x8l [BSTOT*DMODEL];
__device__ __align__(256) uint8_t g_kq8h[2*BSTOT*DMODEL];
__device__ __align__(256) uint8_t g_kq8l[2*BSTOT*DMODEL];
__device__ __align__(256) uint8_t g_w8h [2*DMODEL*DMODEL];
__device__ __align__(256) uint8_t g_w8l [2*DMODEL*DMODEL];

// ---------------- helpers ----------------
__device__ __forceinline__ uint32_t smem_u32(const void* p) {
    uint32_t a;
    asm("{ .reg .u64 t; cvta.to.shared.u64 t, %1; cvt.u32.u64 %0, t; }" : "=r"(a) : "l"(p));
    return a;
}
__device__ __forceinline__ void mmafp16(float c[4], const uint32_t a[4], uint32_t b0, uint32_t b1) {
    asm volatile(
        "mma.sync.aligned.m16n8k16.row.col.f32.f16.f16.f32 "
        "{%0,%1,%2,%3}, {%4,%5,%6,%7}, {%8,%9}, {%0,%1,%2,%3};"
        : "+f"(c[0]), "+f"(c[1]), "+f"(c[2]), "+f"(c[3])
        : "r"(a[0]), "r"(a[1]), "r"(a[2]), "r"(a[3]), "r"(b0), "r"(b1));
}
// fp8 e4m3 mma, zero accumulator -> d
__device__ __forceinline__ void mmafp8z(float d[4], const uint32_t a[4], uint32_t b0, uint32_t b1) {
    asm volatile(
        "mma.sync.aligned.m16n8k32.row.col.f32.e4m3.e4m3.f32 "
        "{%0,%1,%2,%3}, {%4,%5,%6,%7}, {%8,%9}, {%10,%11,%12,%13};"
        : "=f"(d[0]), "=f"(d[1]), "=f"(d[2]), "=f"(d[3])
        : "r"(a[0]), "r"(a[1]), "r"(a[2]), "r"(a[3]), "r"(b0), "r"(b1),
          "f"(0.f), "f"(0.f), "f"(0.f), "f"(0.f));
}
#define LDSM4(r, a) \
    asm volatile("ldmatrix.sync.aligned.m8n8.x4.shared.b16 {%0,%1,%2,%3}, [%4];" \
        : "=r"((r)[0]), "=r"((r)[1]), "=r"((r)[2]), "=r"((r)[3]) : "r"(a))

// pack two floats -> e4m3x2 in a 16-bit reg: byte1=cvt(v1), byte0=cvt(v0)
__device__ __forceinline__ uint16_t cvt_e4m3x2(float v1, float v0) {
    uint16_t p;
    asm("cvt.rn.satfinite.e4m3x2.f32 %0, %1, %2;" : "=h"(p) : "f"(v1), "f"(v0));
    return p;
}

// ---------------- fp16 GEMM w/ optional fp8 cross-split ----------------
// C[M,N] = act(alpha*(A@B^T) + bias)
// SPLIT: A8h/A8l, B8h/B8l fp8 limbs (lo pre-scaled); acc += hi16 + S1*a8h·b8l + S2*a8l·b8h
// block 256x128, BK=32, 256 thr, 8 warps (4M x 2N), warp tile 64x64, 4-stage cp.async.
// Stage SPLIT (48K): Ah16 16K | A8h 8K | A8l 8K | Bh16 8K | B8h 4K | B8l 4K
// Stage plain (24K): Ah16 16K | Bh16 8K

template<bool SPLIT>
__device__ __forceinline__ void issue_tile(
    uint32_t sstage,
    const __half* __restrict__ Ah, const __half* __restrict__ Bh,
    const uint8_t* __restrict__ A8h, const uint8_t* __restrict__ A8l,
    const uint8_t* __restrict__ B8h, const uint8_t* __restrict__ B8l,
    int bm, int bn, int K, int k0, int tid)
{
    if (SPLIT) {
        #pragma unroll
        for (int t = 0; t < 12; ++t) {
            const int c = tid + t * 256;
            const void* src;
            uint32_t off;
            if (c < 1024) {                    // Ah16: 256 rows x 4 chunks
                const int row = c >> 2, ch = c & 3;
                src = Ah + (long long)(bm + row) * K + k0 + ch * 8;
                off = row * 64 + ((ch ^ ((row >> 1) & 3)) << 4);
            } else if (c < 1536) {             // A8h: 256 rows x 2 chunks
                const int i = c - 1024, row = i >> 1, ch = i & 1;
                src = A8h + (long long)(bm + row) * K + k0 + ch * 16;
                off = 16384u + row * 32 + ((ch ^ ((row >> 2) & 1)) << 4);
            } else if (c < 2048) {             // A8l
                const int i = c - 1536, row = i >> 1, ch = i & 1;
                src = A8l + (long long)(bm + row) * K + k0 + ch * 16;
                off = 24576u + row * 32 + ((ch ^ ((row >> 2) & 1)) << 4);
            } else if (c < 2560) {             // Bh16: 128 rows x 4 chunks
                const int i = c - 2048, row = i >> 2, ch = i & 3;
                src = Bh + (long long)(bn + row) * K + k0 + ch * 8;
                off = 32768u + row * 64 + ((ch ^ ((row >> 1) & 3)) << 4);
            } else if (c < 2816) {             // B8h: 128 rows x 2 chunks
                const int i = c - 2560, row = i >> 1, ch = i & 1;
                src = B8h + (long long)(bn + row) * K + k0 + ch * 16;
                off = 40960u + row * 32 + ((ch ^ ((row >> 2) & 1)) << 4);
            } else {                           // B8l
                const int i = c - 2816, row = i >> 1, ch = i & 1;
                src = B8l + (long long)(bn + row) * K + k0 + ch * 16;
                off = 45056u + row * 32 + ((ch ^ ((row >> 2) & 1)) << 4);
            }
            asm volatile("cp.async.cg.shared.global [%0], [%1], 16;"
                         :: "r"(sstage + off), "l"(src));
        }
    } else {
        #pragma unroll
        for (int t = 0; t < 6; ++t) {
            const int c = tid + t * 256;
            const __half* src;
            uint32_t off;
            if (c < 1024) {
                const int row = c >> 2, ch = c & 3;
                src = Ah + (long long)(bm + row) * K + k0 + ch * 8;
                off = row * 64 + ((ch ^ ((row >> 1) & 3)) << 4);
            } else {
                const int c2 = c - 1024, row = c2 >> 2, ch = c2 & 3;
                src = Bh + (long long)(bn + row) * K + k0 + ch * 8;
                off = 16384 + row * 64 + ((ch ^ ((row >> 1) & 3)) << 4);
            }
            asm volatile("cp.async.cg.shared.global [%0], [%1], 16;"
                         :: "r"(sstage + off), "l"(src));
        }
    }
}

template<bool SPLIT, int ACT, bool BIAS, bool OUTF32, bool OUT3, bool OUTH>
__global__ void __launch_bounds__(256, 1)
fp16_gemm(const __half* __restrict__ Ah, const __half* __restrict__ Bh,
          const uint8_t* __restrict__ A8h, const uint8_t* __restrict__ A8l,
          const uint8_t* __restrict__ B8h, const uint8_t* __restrict__ B8l,
          const float* __restrict__ bias, float* __restrict__ Cf,
          __half* __restrict__ Ch, uint8_t* __restrict__ C8h, uint8_t* __restrict__ C8l,
          int K, int N, float alpha, float S1, float S2, float sclOut,
          long long sA, long long sB, long long sC, long long sBias)
{
    constexpr uint32_t STAGE_B = SPLIT ? 49152u : 24576u;
    constexpr uint32_t BOFF16  = SPLIT ? 32768u : 16384u;
    constexpr int NSTAGE       = 4;
    extern __shared__ __align__(16) char smem[];
    Ah += (long long)blockIdx.z * sA;
    Bh += (long long)blockIdx.z * sB;
    if (SPLIT) {
        A8h += (long long)blockIdx.z * sA; A8l += (long long)blockIdx.z * sA;
        B8h += (long long)blockIdx.z * sB; B8l += (long long)blockIdx.z * sB;
    }
    if (BIAS) bias += (long long)blockIdx.z * sBias;
    const int bm = blockIdx.y * 256, bn = blockIdx.x * 128;
    const int tid = threadIdx.x, lane = tid & 31, wid = tid >> 5;
    const int wm = wid & 3, wn = wid >> 2;
    const uint32_t sb = smem_u32(smem);

    const int m1 = (lane >> 3) & 1;
    const int mh = lane >> 4;
    const int lr = lane & 7;

    float acc[4][8][4];
    #pragma unroll
    for (int i = 0; i < 4; i++)
        #pragma unroll
        for (int j = 0; j < 8; j++)
            #pragma unroll
            for (int p = 0; p < 4; p++) acc[i][j][p] = 0.f;

    const int iters = K >> 5;
    #pragma unroll
    for (int s = 0; s < NSTAGE - 1; ++s) {
        issue_tile<SPLIT>(sb + s * STAGE_B, Ah, Bh, A8h, A8l, B8h, B8l, bm, bn, K, s * 32, tid);
        asm volatile("cp.async.commit_group;" ::: "memory");
    }

    for (int t = 0; t < iters; ++t) {
        asm volatile("cp.async.wait_group %0;" :: "n"(NSTAGE - 2) : "memory");
        __syncthreads();
        if (t + NSTAGE - 1 < iters)
            issue_tile<SPLIT>(sb + ((t + NSTAGE - 1) % NSTAGE) * STAGE_B, Ah, Bh,
                              A8h, A8l, B8h, B8l, bm, bn, K, (t + NSTAGE - 1) * 32, tid);
        asm volatile("cp.async.commit_group;" ::: "memory");

        const uint32_t sbase = sb + (t % NSTAGE) * STAGE_B;

        // ---- hi fp16 part ----
        #pragma unroll
        for (int ks = 0; ks < 2; ++ks) {
            uint32_t ah[4][4];
            #pragma unroll
            for (int i = 0; i < 4; ++i) {
                const int rr = wm * 64 + i * 16 + m1 * 8 + lr;
                const int sw = (rr >> 1) & 3;
                LDSM4(ah[i], sbase + rr * 64 + (uint32_t)(((ks * 2 + mh) ^ sw) << 4));
            }
            #pragma unroll
            for (int jp = 0; jp < 4; ++jp) {
                const int rr = wn * 64 + jp * 16 + m1 * 8 + lr;
                const int sw = (rr >> 1) & 3;
                uint32_t bh[4];
                LDSM4(bh, sbase + BOFF16 + rr * 64 + (uint32_t)(((ks * 2 + mh) ^ sw) << 4));
                #pragma unroll
                for (int i = 0; i < 4; ++i) {
                    mmafp16(acc[i][jp * 2],     ah[i], bh[0], bh[2]);
                    mmafp16(acc[i][jp * 2 + 1], ah[i], bh[1], bh[3]);
                }
            }
        }

        // ---- fp8 cross part (k32 per mma) ----
        if (SPLIT) {
            uint32_t a8h[4][4], a8l[4][4];
            #pragma unroll
            for (int i = 0; i < 4; ++i) {
                const int rr = wm * 64 + i * 16 + m1 * 8 + lr;
                const int sw = (rr >> 2) & 1;
                const uint32_t addr = sbase + 16384u + rr * 32 + (uint32_t)(((mh ^ sw)) << 4);
                LDSM4(a8h[i], addr);
                LDSM4(a8l[i], addr + 8192u);
            }
            #pragma unroll
            for (int jp = 0; jp < 4; ++jp) {
                const int rr = wn * 64 + jp * 16 + m1 * 8 + lr;
                const int sw = (rr >> 2) & 1;
                const uint32_t addr = sbase + 40960u + rr * 32 + (uint32_t)(((mh ^ sw)) << 4);
                uint32_t b8h[4], b8l[4];
                LDSM4(b8h, addr);
                LDSM4(b8l, addr + 4096u);
                #pragma unroll
                for (int i = 0; i < 4; ++i) {
                    float d[4];
                    mmafp8z(d, a8h[i], b8l[0], b8l[2]);
                    #pragma unroll
                    for (int p = 0; p < 4; ++p) acc[i][jp*2][p] = fmaf(S1, d[p], acc[i][jp*2][p]);
                    mmafp8z(d, a8h[i], b8l[1], b8l[3]);
                    #pragma unroll
                    for (int p = 0; p < 4; ++p) acc[i][jp*2+1][p] = fmaf(S1, d[p], acc[i][jp*2+1][p]);
                    mmafp8z(d, a8l[i], b8h[0], b8h[2]);
                    #pragma unroll
                    for (int p = 0; p < 4; ++p) acc[i][jp*2][p] = fmaf(S2, d[p], acc[i][jp*2][p]);
                    mmafp8z(d, a8l[i], b8h[1], b8h[3]);
                    #pragma unroll
                    for (int p = 0; p < 4; ++p) acc[i][jp*2+1][p] = fmaf(S2, d[p], acc[i][jp*2+1][p]);
                }
            }
        }
        __syncthreads();
    }

    // ---------------- epilogue ----------------
    #pragma unroll
    for (int i = 0; i < 4; ++i) {
        const long long r0 = bm + wm * 64 + i * 16 + (lane >> 2);
        #pragma unroll
        for (int j = 0; j < 8; ++j) {
            const int c0 = bn + wn * 64 + j * 8 + (lane & 3) * 2;
            float v0 = acc[i][j][0] * alpha;
            float v1 = acc[i][j][1] * alpha;
            float v2 = acc[i][j][2] * alpha;
            float v3 = acc[i][j][3] * alpha;
            if (BIAS) {
                float2 bb = *(const float2*)(bias + c0);
                v0 += bb.x; v1 += bb.y; v2 += bb.x; v3 += bb.y;
            }
            if (ACT == 1) {
                v0 = 0.5f * v0 * (1.0f + erff(v0 * 0.7071067811865475f));
                v1 = 0.5f * v1 * (1.0f + erff(v1 * 0.7071067811865475f));
                v2 = 0.5f * v2 * (1.0f + erff(v2 * 0.7071067811865475f));
                v3 = 0.5f * v3 * (1.0f + erff(v3 * 0.7071067811865475f));
            }
            const long long off0 = (long long)blockIdx.z * sC + r0 * N + c0;
            const long long off1 = off0 + 8LL * N;
            if (OUTF32) {
                *(float2*)(Cf + off0) = make_float2(v0, v1);
                *(float2*)(Cf + off1) = make_float2(v2, v3);
            }
            if (OUT3) {
                __half h0 = __float2half(v0), h1 = __float2half(v1);
                __half h2 = __float2half(v2), h3 = __float2half(v3);
                __half2 hh01; hh01.x = h0; hh01.y = h1;
                __half2 hh23; hh23.x = h2; hh23.y = h3;
                *(__half2*)(Ch + off0) = hh01;
                *(__half2*)(Ch + off1) = hh23;
                *(uint16_t*)(C8h + off0) = cvt_e4m3x2(v1, v0);
                *(uint16_t*)(C8h + off1) = cvt_e4m3x2(v3, v2);
                *(uint16_t*)(C8l + off0) = cvt_e4m3x2(
                    (v1 - __half2float(h1)) * sclOut, (v0 - __half2float(h0)) * sclOut);
                *(uint16_t*)(C8l + off1) = cvt_e4m3x2(
                    (v3 - __half2float(h3)) * sclOut, (v2 - __half2float(h2)) * sclOut);
            }
            if (OUTH) {
                *(__half2*)(Ch + off0) = __floats2half2_rn(v0, v1);
                *(__half2*)(Ch + off1) = __floats2half2_rn(v2, v3);
            }
        }
    }
}

// ---------------- transpose + convert (fp16 hi only) ----------------
__global__ void transpose_convert(const float* __restrict__ in,
                                  __half* __restrict__ oh,
                                  int R, int C, long long sIn, long long sOut)
{
    __shared__ float t[32][33];
    in += (long long)blockIdx.z * sIn;
    oh += (long long)blockIdx.z * sOut;
    const int c0 = blockIdx.x * 32, r0 = blockIdx.y * 32;
    #pragma unroll
    for (int j = 0; j < 32; j += 8)
        t[threadIdx.y + j][threadIdx.x] =
            in[(long long)(r0 + threadIdx.y + j) * C + c0 + threadIdx.x];
    __syncthreads();
    #pragma unroll
    for (int j = 0; j < 32; j += 8) {
        const float v = t[threadIdx.x][threadIdx.y + j];
        oh[(long long)(c0 + threadIdx.y + j) * R + r0 + threadIdx.x] = __float2half(v);
    }
}

// qkv transpose: z=0 wk, z=1 wq -> h16 + fp8 limbs; z=2 wv -> h16 only
__global__ void transpose_qkv(const float* __restrict__ wk, const float* __restrict__ wq,
                              const float* __restrict__ wv,
                              __half* __restrict__ kqh, uint8_t* __restrict__ w8h,
                              uint8_t* __restrict__ w8l, __half* __restrict__ vh)
{
    __shared__ float t[32][33];
    const int which = blockIdx.z;
    const float* in = (which == 0) ? wk : (which == 1) ? wq : wv;
    const long long wbase = (long long)which * DMODEL * DMODEL;
    const int c0 = blockIdx.x * 32, r0 = blockIdx.y * 32;
    #pragma unroll
    for (int j = 0; j < 32; j += 8)
        t[threadIdx.y + j][threadIdx.x] =
            in[(long long)(r0 + threadIdx.y + j) * DMODEL + c0 + threadIdx.x];
    __syncthreads();
    #pragma unroll
    for (int j = 0; j < 32; j += 8) {
        const float v = t[threadIdx.x][threadIdx.y + j];
        const __half h = __float2half(v);
        const long long o = (long long)(c0 + threadIdx.y + j) * DMODEL + r0 + threadIdx.x;
        if (which == 2) {
            vh[o] = h;
        } else {
            kqh[wbase + o] = h;
            w8h[wbase + o] = (uint8_t)(cvt_e4m3x2(0.f, v) & 0xFFu);
            w8l[wbase + o] = (uint8_t)(cvt_e4m3x2(0.f, (v - __half2float(h)) * SCL_W) & 0xFFu);
        }
    }
}

__global__ void concat_bias(const float* __restrict__ bk, const float* __restrict__ bq,
                            float* __restrict__ o)
{
    const int i = blockIdx.x * 256 + threadIdx.x;
    o[i] = (i < DMODEL) ? bk[i] : bq[i - DMODEL];
}

// ---------------- pos + embedding ----------------
__global__ void pos_kernel(float* __restrict__ tab) {
    const int s = blockIdx.x;
    #pragma unroll
    for (int j = 0; j < 2; ++j) {
        const int d = threadIdx.x + j * 256;
        const float f = powf(10000.0f, -2.0f * (float)d / 512.0f);
        const float ang = (float)s * f;
        tab[s * DMODEL + d] = ((d & 1) == 0) ? sinf(ang) : cosf(ang);
    }
}

__global__ void embed_kernel(const int* __restrict__ seq, const float* __restrict__ emb,
                             const float* __restrict__ tab, float* __restrict__ x,
                             __half* __restrict__ xh, uint8_t* __restrict__ x8h,
                             uint8_t* __restrict__ x8l)
{
    const int row = blockIdx.x;
    const int s = row & (SEQ - 1);
    const int tok = seq[row];
    const int d0 = threadIdx.x * 4;
    const float sc = 22.627416997969522f;
    float4 e = *(const float4*)(emb + (long long)tok * DMODEL + d0);
    float4 p = *(const float4*)(tab + s * DMODEL + d0);
    float4 o = { (e.x + p.x) * sc, (e.y + p.y) * sc, (e.z + p.z) * sc, (e.w + p.w) * sc };
    const long long base = (long long)row * DMODEL + d0;
    *(float4*)(x + base) = o;
    __half h0 = __float2half(o.x), h1 = __float2half(o.y);
    __half h2 = __float2half(o.z), h3 = __float2half(o.w);
    __half2 a; a.x = h0; a.y = h1;
    __half2 b; b.x = h2; b.y = h3;
    *(__half2*)(xh + base) = a;
    *(__half2*)(xh + base + 2) = b;
    uint16_t p01 = cvt_e4m3x2(o.y, o.x);
    uint16_t p23 = cvt_e4m3x2(o.w, o.z);
    *(uint32_t*)(x8h + base) = ((uint32_t)p23 << 16) | (uint32_t)p01;
    uint16_t l01 = cvt_e4m3x2((o.y - __half2float(h1)) * SCL_X, (o.x - __half2float(h0)) * SCL_X);
    uint16_t l23 = cvt_e4m3x2((o.w - __half2float(h3)) * SCL_X, (o.z - __half2float(h2)) * SCL_X);
    *(uint32_t*)(x8l + base) = ((uint32_t)l23 << 16) | (uint32_t)l01;
}

// ---------------- block reductions ----------------
template<int NT>
__device__ __forceinline__ float blockSum(float v, float* sm) {
    #pragma unroll
    for (int o = 16; o > 0; o >>= 1) v += __shfl_xor_sync(0xffffffffu, v, o);
    const int w = threadIdx.x >> 5;
    if ((threadIdx.x & 31) == 0) sm[w] = v;
    __syncthreads();
    if (threadIdx.x < 32) {
        float x = (threadIdx.x < NT / 32) ? sm[threadIdx.x] : 0.f;
        #pragma unroll
        for (int o = NT / 64; o > 0; o >>= 1) x += __shfl_xor_sync(0xffffffffu, x, o);
        if (threadIdx.x == 0) sm[0] = x;
    }
    __syncthreads();
    float r = sm[0];
    __syncthreads();
    return r;
}
template<int NT>
__device__ __forceinline__ float blockMax(float v, float* sm) {
    #pragma unroll
    for (int o = 16; o > 0; o >>= 1) v = fmaxf(v, __shfl_xor_sync(0xffffffffu, v, o));
    const int w = threadIdx.x >> 5;
    if ((threadIdx.x & 31) == 0) sm[w] = v;
    __syncthreads();
    if (threadIdx.x < 32) {
        float x = (threadIdx.x < NT / 32) ? sm[threadIdx.x] : -INFINITY;
        #pragma unroll
        for (int o = NT / 64; o > 0; o >>= 1) x = fmaxf(x, __shfl_xor_sync(0xffffffffu, x, o));
        if (threadIdx.x == 0) sm[0] = x;
    }
    __syncthreads();
    float r = sm[0];
    __syncthreads();
    return r;
}

// ---------------- softmax (fp32 in, fp16 out) ----------------
__global__ void softmax_kernel(const float* __restrict__ S, __half* __restrict__ ph)
{
    __shared__ float sm[8];
    const long long base = (long long)blockIdx.x * SEQ;
    const float* row = S + base;
    const int t = threadIdx.x;
    float vals[8];
    float m = -INFINITY;
    #pragma unroll
    for (int i = 0; i < 8; i++) { vals[i] = row[t + i * 256]; m = fmaxf(m, vals[i]); }
    m = blockMax<256>(m, sm);
    float s = 0.f;
    #pragma unroll
    for (int i = 0; i < 8; i++) { vals[i] = expf(vals[i] - m); s += vals[i]; }
    s = blockSum<256>(s, sm);
    const float inv = 1.f / s;
    #pragma unroll
    for (int i = 0; i < 8; i++)
        ph[base + t + i * 256] = __float2half(vals[i] * inv);
}

// ---------------- fused add + LayerNorm ----------------
template<bool H16>
__global__ void add_ln_kernel(const float* __restrict__ a, const float* __restrict__ b,
                              const float* __restrict__ gamma, const float* __restrict__ beta,
                              float* __restrict__ out, __half* __restrict__ oh)
{
    __shared__ float sm[4];
    const long long base = (long long)blockIdx.x * DMODEL;
    const int d0 = threadIdx.x * 4;
    float4 av = *(const float4*)(a + base + d0);
    float4 bv = *(const float4*)(b + base + d0);
    float z[4] = { av.x + bv.x, av.y + bv.y, av.z + bv.z, av.w + bv.w };
    float s = z[0] + z[1] + z[2] + z[3];
    s = blockSum<128>(s, sm);
    const float mu = s * (1.0f / DMODEL);
    float vs = 0.f;
    #pragma unroll
    for (int i = 0; i < 4; i++) { float dz = z[i] - mu; vs += dz * dz; }
    vs = blockSum<128>(vs, sm);
    const float rstd = rsqrtf(vs * (1.0f / DMODEL) + 1e-5f);
    float4 gv = *(const float4*)(gamma + d0);
    float4 bvv = *(const float4*)(beta + d0);
    float4 o;
    o.x = (z[0] - mu) * rstd * gv.x + bvv.x;
    o.y = (z[1] - mu) * rstd * gv.y + bvv.y;
    o.z = (z[2] - mu) * rstd * gv.z + bvv.z;
    o.w = (z[3] - mu) * rstd * gv.w + bvv.w;
    *(float4*)(out + base + d0) = o;
    if (H16) {
        *(__half2*)(oh + base + d0)     = __floats2half2_rn(o.x, o.y);
        *(__half2*)(oh + base + d0 + 2) = __floats2half2_rn(o.z, o.w);
    }
}

// ---------------- launch ----------------
#define SMEM_SPLIT (4 * 49152)   // 196608
#define SMEM_PLAIN (4 * 24576)   // 98304

extern "C" void kernel_launch(void* const* d_in, const int* in_sizes, int n_in,
                              void* d_out, int out_size)
{
    const int*   seq  = (const int*)  d_in[0];
    const float* emb  = (const float*)d_in[1];
    const float* wk   = (const float*)d_in[2];
    const float* bk   = (const float*)d_in[3];
    const float* wq   = (const float*)d_in[4];
    const float* bq   = (const float*)d_in[5];
    const float* wv   = (const float*)d_in[6];
    const float* bv   = (const float*)d_in[7];
    const float* ln_g = (const float*)d_in[8];
    const float* ln_b = (const float*)d_in[9];
    const float* w1   = (const float*)d_in[10];
    const float* b1   = (const float*)d_in[11];
    const float* w2   = (const float*)d_in[12];
    const float* b2   = (const float*)d_in[13];
    float* out = (float*)d_out;

    float *x, *v, *at, *r, *f2, *sc, *pos, *bkq;
    __half *xh, *kqh, *vTh, *rh, *ph, *f1h, *wkqTh, *wvTh, *w1Th, *w2Th;
    uint8_t *x8h, *x8l, *kq8h, *kq8l, *w8h, *w8l;
    cudaGetSymbolAddress((void**)&x,     g_x);
    cudaGetSymbolAddress((void**)&v,     g_v);
    cudaGetSymbolAddress((void**)&at,    g_at);
    cudaGetSymbolAddress((void**)&r,     g_r);
    cudaGetSymbolAddress((void**)&f2,    g_f2);
    cudaGetSymbolAddress((void**)&sc,    g_sc);
    cudaGetSymbolAddress((void**)&pos,   g_pos);
    cudaGetSymbolAddress((void**)&bkq,   g_bkq);
    cudaGetSymbolAddress((void**)&xh,    g_xh);
    cudaGetSymbolAddress((void**)&kqh,   g_kqh);
    cudaGetSymbolAddress((void**)&vTh,   g_vTh);
    cudaGetSymbolAddress((void**)&rh,    g_rh);
    cudaGetSymbolAddress((void**)&ph,    g_ph);
    cudaGetSymbolAddress((void**)&f1h,   g_f1h);
    cudaGetSymbolAddress((void**)&wkqTh, g_wkqTh);
    cudaGetSymbolAddress((void**)&wvTh,  g_wvTh);
    cudaGetSymbolAddress((void**)&w1Th,  g_w1Th);
    cudaGetSymbolAddress((void**)&w2Th,  g_w2Th);
    cudaGetSymbolAddress((void**)&x8h,   g_x8h);
    cudaGetSymbolAddress((void**)&x8l,   g_x8l);
    cudaGetSymbolAddress((void**)&kq8h,  g_kq8h);
    cudaGetSymbolAddress((void**)&kq8l,  g_kq8l);
    cudaGetSymbolAddress((void**)&w8h,   g_w8h);
    cudaGetSymbolAddress((void**)&w8l,   g_w8l);

    __half*  kh  = kqh;
    __half*  qh  = kqh + (long long)BSTOT * DMODEL;
    uint8_t* k8h = kq8h;
    uint8_t* k8l = kq8l;
    uint8_t* q8h = kq8h + (long long)BSTOT * DMODEL;
    uint8_t* q8l = kq8l + (long long)BSTOT * DMODEL;

    cudaFuncSetAttribute(fp16_gemm<true,  0, true,  false, true,  false>, cudaFuncAttributeMaxDynamicSharedMemorySize, SMEM_SPLIT);
    cudaFuncSetAttribute(fp16_gemm<true,  0, false, true,  false, false>, cudaFuncAttributeMaxDynamicSharedMemorySize, SMEM_SPLIT);
    cudaFuncSetAttribute(fp16_gemm<false, 0, true,  true,  false, false>, cudaFuncAttributeMaxDynamicSharedMemorySize, SMEM_PLAIN);
    cudaFuncSetAttribute(fp16_gemm<false, 0, false, true,  false, false>, cudaFuncAttributeMaxDynamicSharedMemorySize, SMEM_PLAIN);
    cudaFuncSetAttribute(fp16_gemm<false, 1, true,  false, false, true >, cudaFuncAttributeMaxDynamicSharedMemorySize, SMEM_PLAIN);

    dim3 tb(32, 8);

    pos_kernel<<<SEQ, 256>>>(pos);
    embed_kernel<<<BSTOT, 128>>>(seq, emb, pos, x, xh, x8h, x8l);
    concat_bias<<<4, 256>>>(bk, bq, bkq);
    transpose_qkv<<<dim3(16, 16, 3), tb>>>(wk, wq, wv, wkqTh, w8h, w8l, wvTh);

    // fused k+q projection: hi fp16 + fp8 cross (S1 = 1/SCL_W for xh·wl, S2 = 1/SCL_X for xl·wh)
    fp16_gemm<true, 0, true, false, true, false><<<dim3(4, 32, 2), 256, SMEM_SPLIT>>>(
        xh, wkqTh, x8h, x8l, w8h, w8l, bkq, nullptr, kqh, kq8h, kq8l,
        DMODEL, DMODEL, 1.f, 1.0f / SCL_W, 1.0f / SCL_X, SCL_KQ,
        0, (long long)DMODEL * DMODEL, (long long)BSTOT * DMODEL, DMODEL);
    // v projection (plain)
    fp16_gemm<false, 0, true, true, false, false><<<dim3(4, 32, 1), 256, SMEM_PLAIN>>>(
        xh, wvTh, nullptr, nullptr, nullptr, nullptr, bv, v, nullptr, nullptr, nullptr,
        DMODEL, DMODEL, 1.f, 0.f, 0.f, 0.f, 0, 0, 0, 0);

    transpose_convert<<<dim3(64, 16, 1), tb>>>(w1, w1Th, DMODEL, DFFN, 0, 0);
    transpose_convert<<<dim3(16, 64, 1), tb>>>(w2, w2Th, DFFN, DMODEL, 0, 0);
    transpose_convert<<<dim3(16, 64, NBATCH), tb>>>(v, vTh, SEQ, DMODEL,
        (long long)SEQ * DMODEL, (long long)DMODEL * SEQ);

    // scores = k @ q^T / sqrt(D): hi fp16 + fp8 cross (S1 = S2 = 1/SCL_KQ)
    fp16_gemm<true, 0, false, true, false, false><<<dim3(16, 8, NBATCH), 256, SMEM_SPLIT>>>(
        kh, qh, k8h, k8l, q8h, q8l, nullptr, sc, nullptr, nullptr, nullptr,
        DMODEL, SEQ, 0.044194173824159216f, 1.0f / SCL_KQ, 1.0f / SCL_KQ, 0.f,
        (long long)SEQ * DMODEL, (long long)SEQ * DMODEL, (long long)SEQ * SEQ, 0);

    softmax_kernel<<<NBATCH * SEQ, 256>>>(sc, ph);

    // attn = P @ V  (plain fp16)
    fp16_gemm<false, 0, false, true, false, false><<<dim3(4, 8, NBATCH), 256, SMEM_PLAIN>>>(
        ph, vTh, nullptr, nullptr, nullptr, nullptr, nullptr, at, nullptr, nullptr, nullptr,
        SEQ, DMODEL, 1.f, 0.f, 0.f, 0.f,
        (long long)SEQ * SEQ, (long long)DMODEL * SEQ, (long long)SEQ * DMODEL, 0);

    add_ln_kernel<true><<<BSTOT, 128>>>(x, at, ln_g, ln_b, r, rh);

    // FFN (plain fp16)
    fp16_gemm<false, 1, true, false, false, true><<<dim3(16, 32, 1), 256, SMEM_PLAIN>>>(
        rh, w1Th, nullptr, nullptr, nullptr, nullptr, b1, nullptr, f1h, nullptr, nullptr,
        DMODEL, DFFN, 1.f, 0.f, 0.f, 0.f, 0, 0, 0, 0);
    fp16_gemm<false, 0, true, true, false, false><<<dim3(4, 32, 1), 256, SMEM_PLAIN>>>(
        f1h, w2Th, nullptr, nullptr, nullptr, nullptr, b2, f2, nullptr, nullptr, nullptr,
        DFFN, DMODEL, 1.f, 0.f, 0.f, 0.f, 0, 0, 0, 0);

    add_ln_kernel<false><<<BSTOT, 128>>>(r, f2, ln_g, ln_b, out, nullptr);
}